// round 2
// baseline (speedup 1.0000x reference)
#include <cuda_runtime.h>
#include <cuda_bf16.h>
#include <cstdint>
#include <cstddef>

// Problem constants
#define T_TOK   4096      // B*S
#define DDIM    1024
#define HDIM    4096
#define NEXP    8
#define CAP     2048
#define NSLOT   (T_TOK*2) // K=2

// GEMM tiling
#define BM 128
#define BN 128
#define BKT 16
#define ASTRIDE 20    // padded A row stride (floats), 16B-aligned chunks, conflict-free
#define BSTRIDE 132   // padded B row stride (floats)

// ---------------- device scratch (allocation-free rule: device globals) ----
__device__ float g_hbuf[(size_t)NEXP * CAP * HDIM];   // 256 MB intermediate h
__device__ int   g_eidx[NSLOT];
__device__ float g_gate[NSLOT];
__device__ int   g_arow[NEXP * CAP];    // gather offsets (token*DDIM) per expert row
__device__ int   g_rowinfo[NEXP * CAP]; // slot index per expert row
__device__ int   g_counts[NEXP];
__device__ float g_partial[512 * NEXP]; // per-block router prob partial sums

// ---------------- small PTX helpers ----------------
__device__ __forceinline__ void cp_async16(void* smem, const void* gmem) {
    uint32_t s = (uint32_t)__cvta_generic_to_shared(smem);
    asm volatile("cp.async.cg.shared.global [%0], [%1], 16;\n" :: "r"(s), "l"(gmem));
}
__device__ __forceinline__ void cp_commit() { asm volatile("cp.async.commit_group;\n"); }
__device__ __forceinline__ void cp_wait1() { asm volatile("cp.async.wait_group 1;\n"); }
__device__ __forceinline__ void cp_wait0() { asm volatile("cp.async.wait_group 0;\n"); }

__device__ __forceinline__ uint32_t f2tf32(float v) {
    uint32_t r;
    asm("cvt.rna.tf32.f32 %0, %1;" : "=r"(r) : "f"(v));
    return r;
}
__device__ __forceinline__ void mma_tf32(float* d, const uint32_t* a, const uint32_t* b) {
    asm volatile(
        "mma.sync.aligned.m16n8k8.row.col.f32.tf32.tf32.f32 "
        "{%0,%1,%2,%3}, {%4,%5,%6,%7}, {%8,%9}, {%0,%1,%2,%3};\n"
        : "+f"(d[0]), "+f"(d[1]), "+f"(d[2]), "+f"(d[3])
        : "r"(a[0]), "r"(a[1]), "r"(a[2]), "r"(a[3]), "r"(b[0]), "r"(b[1]));
}
__device__ __forceinline__ float gelu_exact(float v) {
    return 0.5f * v * (1.0f + erff(v * 0.70710678118654752440f));
}

// ---------------- router: logits -> softmax -> top2 -> gates ----------------
// 1 warp per token, 8 tokens per block, grid = 512
__global__ __launch_bounds__(256) void router_kernel(
    const float* __restrict__ x, const float* __restrict__ rw)
{
    __shared__ float srw[NEXP * DDIM];       // 32 KB
    __shared__ float sp[8][NEXP];            // per-warp probs for deterministic block sum
    int tid = threadIdx.x;
    for (int i = tid; i < NEXP * DDIM; i += 256) srw[i] = rw[i];
    __syncthreads();

    int warp = tid >> 5, lane = tid & 31;
    int t = blockIdx.x * 8 + warp;

    float acc[NEXP];
#pragma unroll
    for (int e = 0; e < NEXP; e++) acc[e] = 0.f;

    const float* xr = x + (size_t)t * DDIM;
    for (int d = lane; d < DDIM; d += 32) {
        float xv = xr[d];
#pragma unroll
        for (int e = 0; e < NEXP; e++) acc[e] += xv * srw[e * DDIM + d];
    }
#pragma unroll
    for (int off = 16; off; off >>= 1) {
#pragma unroll
        for (int e = 0; e < NEXP; e++)
            acc[e] += __shfl_down_sync(0xffffffffu, acc[e], off);
    }
    if (lane == 0) {
        float m = acc[0];
#pragma unroll
        for (int e = 1; e < NEXP; e++) m = fmaxf(m, acc[e]);
        float p[NEXP], s = 0.f;
#pragma unroll
        for (int e = 0; e < NEXP; e++) { p[e] = expf(acc[e] - m); s += p[e]; }
        float inv = 1.0f / s;
#pragma unroll
        for (int e = 0; e < NEXP; e++) p[e] *= inv;

        // top-2, first-index wins on ties (matches lax.top_k)
        int e1 = 0;
#pragma unroll
        for (int e = 1; e < NEXP; e++) if (p[e] > p[e1]) e1 = e;
        int e2 = (e1 == 0) ? 1 : 0;
#pragma unroll
        for (int e = 0; e < NEXP; e++) if (e != e1 && p[e] > p[e2]) e2 = e;

        float denom = p[e1] + p[e2];
        g_eidx[2 * t]     = e1;  g_gate[2 * t]     = p[e1] / denom;
        g_eidx[2 * t + 1] = e2;  g_gate[2 * t + 1] = p[e2] / denom;
#pragma unroll
        for (int e = 0; e < NEXP; e++) sp[warp][e] = p[e];
    }
    __syncthreads();
    if (tid < NEXP) {
        float s = 0.f;
#pragma unroll
        for (int w = 0; w < 8; w++) s += sp[w][tid];
        g_partial[blockIdx.x * NEXP + tid] = s;
    }
}

// ---------------- deterministic capacity scan (1 block) ----------------
__global__ __launch_bounds__(256) void scan_kernel(float* __restrict__ lb_out)
{
    __shared__ int cnt[256][NEXP];   // 8 KB
    __shared__ int tot[NEXP];
    int tid = threadIdx.x;

    // default gather offset = token 0 (rows past count are never combined)
    for (int i = tid; i < NEXP * CAP; i += 256) g_arow[i] = 0;

    int base = tid * 32;
    int lc[NEXP];
#pragma unroll
    for (int e = 0; e < NEXP; e++) lc[e] = 0;
    for (int i = 0; i < 32; i++) lc[g_eidx[base + i]]++;
#pragma unroll
    for (int e = 0; e < NEXP; e++) cnt[tid][e] = lc[e];
    __syncthreads();

    if (tid < NEXP) {   // sequential exclusive scan per expert (deterministic)
        int s = 0;
        for (int j = 0; j < 256; j++) { int v = cnt[j][tid]; cnt[j][tid] = s; s += v; }
        tot[tid] = s;
        g_counts[tid] = (s < CAP) ? s : CAP;
    }
    __syncthreads();

    int run[NEXP];
#pragma unroll
    for (int e = 0; e < NEXP; e++) run[e] = cnt[tid][e];
    for (int i = 0; i < 32; i++) {
        int slot = base + i;
        int e = g_eidx[slot];
        int pos = run[e]++;
        if (pos < CAP) {
            g_rowinfo[e * CAP + pos] = slot;
            g_arow[e * CAP + pos] = (slot >> 1) * DDIM;
        }
    }

    if (tid == 0) {
        float lb = 0.f;
        for (int e = 0; e < NEXP; e++) {
            float ps = 0.f;
            for (int b = 0; b < 512; b++) ps += g_partial[b * NEXP + e];
            lb += (ps / (float)T_TOK) * ((float)tot[e] / (float)NSLOT);
        }
        *lb_out = lb * (float)NEXP;
    }
}

// ---------------- tf32 GEMM: EPI 0 = gather-A + GELU->hbuf, EPI 1 = scatter-add out
template <int EPI>
__global__ __launch_bounds__(256, 2) void moe_gemm(
    const float* __restrict__ Ax,     // EPI0: x base; EPI1: unused
    const float* __restrict__ Bbase,  // w1 or w2 (E x K x N)
    const float* __restrict__ bias,   // b1 or b2 (E x N)
    float* __restrict__ outp,         // EPI1: out base; EPI0: unused
    int Kdim, int Ncols)
{
    __shared__ float As[2][BM * ASTRIDE];
    __shared__ float Bs[2][BKT * BSTRIDE];
    __shared__ const float* Arows[BM];

    const int e = blockIdx.z;
    const int m0blk = blockIdx.y * BM;
    const int n0blk = blockIdx.x * BN;
    const int tid = threadIdx.x;

    if (tid < BM) {
        int gm = m0blk + tid;
        const float* p;
        if (EPI == 0) p = Ax + g_arow[e * CAP + gm];
        else          p = g_hbuf + (size_t)(e * CAP + gm) * Kdim;
        Arows[tid] = p;
    }
    const float* Bexp = Bbase + (size_t)e * Kdim * Ncols;
    const float* brow = bias + e * Ncols;
    __syncthreads();

    const int warp = tid >> 5, lane = tid & 31;
    const int wm = (warp >> 2) * 64;
    const int wn = (warp & 3) * 32;
    const int grp = lane >> 2, qid = lane & 3;

    float acc[4][4][4];
#pragma unroll
    for (int mi = 0; mi < 4; mi++)
#pragma unroll
        for (int ni = 0; ni < 4; ni++)
#pragma unroll
            for (int j = 0; j < 4; j++) acc[mi][ni][j] = 0.f;

    const int nk = Kdim / BKT;

    auto issue = [&](int buf, int kt) {
        int k0 = kt * BKT;
#pragma unroll
        for (int i = 0; i < 2; i++) {                 // A: 512 x 16B chunks
            int c = i * 256 + tid;
            int r = c >> 2;
            int kc = (c & 3) * 4;
            cp_async16(&As[buf][r * ASTRIDE + kc], Arows[r] + k0 + kc);
        }
#pragma unroll
        for (int i = 0; i < 2; i++) {                 // B: 512 x 16B chunks
            int c = i * 256 + tid;
            int kr = c >> 5;
            int cc = (c & 31) * 4;
            cp_async16(&Bs[buf][kr * BSTRIDE + cc],
                       Bexp + (size_t)(k0 + kr) * Ncols + n0blk + cc);
        }
        cp_commit();
    };

    issue(0, 0);
    for (int kt = 0; kt < nk; ++kt) {
        int cur = kt & 1;
        if (kt + 1 < nk) { issue(cur ^ 1, kt + 1); cp_wait1(); }
        else             { cp_wait0(); }
        __syncthreads();

#pragma unroll
        for (int kk = 0; kk < BKT; kk += 8) {
            uint32_t afr[4][4];
#pragma unroll
            for (int mi = 0; mi < 4; mi++) {
                int r = wm + mi * 16 + grp;
                const float* a0 = &As[cur][r * ASTRIDE + kk + qid];
                const float* a1 = &As[cur][(r + 8) * ASTRIDE + kk + qid];
                afr[mi][0] = f2tf32(a0[0]);
                afr[mi][1] = f2tf32(a1[0]);
                afr[mi][2] = f2tf32(a0[4]);
                afr[mi][3] = f2tf32(a1[4]);
            }
            uint32_t bfr[4][2];
#pragma unroll
            for (int ni = 0; ni < 4; ni++) {
                int ccol = wn + ni * 8 + grp;
                bfr[ni][0] = f2tf32(Bs[cur][(kk + qid) * BSTRIDE + ccol]);
                bfr[ni][1] = f2tf32(Bs[cur][(kk + qid + 4) * BSTRIDE + ccol]);
            }
#pragma unroll
            for (int mi = 0; mi < 4; mi++)
#pragma unroll
                for (int ni = 0; ni < 4; ni++)
                    mma_tf32(acc[mi][ni], afr[mi], bfr[ni]);
        }
        __syncthreads();
    }

    // ---------------- epilogue ----------------
    if (EPI == 0) {
#pragma unroll
        for (int mi = 0; mi < 4; mi++) {
            int r0 = m0blk + wm + mi * 16 + grp;
            int r1 = r0 + 8;
#pragma unroll
            for (int ni = 0; ni < 4; ni++) {
                int c0 = n0blk + wn + ni * 8 + qid * 2;
                float b0  = brow[c0];
                float b1v = brow[c0 + 1];
                size_t o0 = (size_t)(e * CAP + r0) * Ncols + c0;
                size_t o1 = (size_t)(e * CAP + r1) * Ncols + c0;
                g_hbuf[o0]     = gelu_exact(acc[mi][ni][0] + b0);
                g_hbuf[o0 + 1] = gelu_exact(acc[mi][ni][1] + b1v);
                g_hbuf[o1]     = gelu_exact(acc[mi][ni][2] + b0);
                g_hbuf[o1 + 1] = gelu_exact(acc[mi][ni][3] + b1v);
            }
        }
    } else {
        int cnt = g_counts[e];
#pragma unroll
        for (int mi = 0; mi < 4; mi++) {
            int r0 = m0blk + wm + mi * 16 + grp;
            int r1 = r0 + 8;
            int slot0 = (r0 < cnt) ? g_rowinfo[e * CAP + r0] : -1;
            int slot1 = (r1 < cnt) ? g_rowinfo[e * CAP + r1] : -1;
            float gf0 = (slot0 >= 0) ? g_gate[slot0] : 0.f;
            float gf1 = (slot1 >= 0) ? g_gate[slot1] : 0.f;
            int tok0 = (slot0 >= 0) ? (slot0 >> 1) : 0;
            int tok1 = (slot1 >= 0) ? (slot1 >> 1) : 0;
#pragma unroll
            for (int ni = 0; ni < 4; ni++) {
                int c0 = n0blk + wn + ni * 8 + qid * 2;
                float b0  = brow[c0];
                float b1v = brow[c0 + 1];
                if (slot0 >= 0) {
                    atomicAdd(&outp[(size_t)tok0 * DDIM + c0],     gf0 * (acc[mi][ni][0] + b0));
                    atomicAdd(&outp[(size_t)tok0 * DDIM + c0 + 1], gf0 * (acc[mi][ni][1] + b1v));
                }
                if (slot1 >= 0) {
                    atomicAdd(&outp[(size_t)tok1 * DDIM + c0],     gf1 * (acc[mi][ni][2] + b0));
                    atomicAdd(&outp[(size_t)tok1 * DDIM + c0 + 1], gf1 * (acc[mi][ni][3] + b1v));
                }
            }
        }
    }
}

// ---------------- launch ----------------
extern "C" void kernel_launch(void* const* d_in, const int* in_sizes, int n_in,
                              void* d_out, int out_size)
{
    (void)in_sizes; (void)n_in; (void)out_size;
    const float* x   = (const float*)d_in[0];
    const float* rw  = (const float*)d_in[1];
    const float* w1  = (const float*)d_in[2];
    const float* b1  = (const float*)d_in[3];
    const float* w2  = (const float*)d_in[4];
    const float* b2  = (const float*)d_in[5];
    float* out = (float*)d_out;

    // zero the combine target (out region only); lb_loss lives at index T*D
    cudaMemsetAsync(out, 0, (size_t)T_TOK * DDIM * sizeof(float));

    router_kernel<<<T_TOK / 8, 256>>>(x, rw);
    scan_kernel<<<1, 256>>>(out + (size_t)T_TOK * DDIM);

    dim3 g1(HDIM / BN, CAP / BM, NEXP);   // 32 x 16 x 8
    moe_gemm<0><<<g1, 256>>>(x, w1, b1, nullptr, DDIM, HDIM);

    dim3 g2(DDIM / BN, CAP / BM, NEXP);   // 8 x 16 x 8
    moe_gemm<1><<<g2, 256>>>(nullptr, w2, b2, out, HDIM, DDIM);
}